// round 1
// baseline (speedup 1.0000x reference)
#include <cuda_runtime.h>
#include <math.h>

#define NV 6890
#define CIN 3
#define RR 5
#define AA 8
#define RA 40          // RR*AA
#define NROT 8
#define TT 100
#define NCOL 800       // NROT*TT
#define KMAX (RA*TT)   // 4000

// ---- scratch (device globals; no allocation at runtime) ----
__device__ float g_x[NV * TT];             // current features (C<=100)
__device__ float g_patch[(size_t)NV * RA * TT];    // 27.56M floats
__device__ float g_B[KMAX * NCOL];          // rotated weight matrix (K x 800)
__device__ float g_conv[NV * NCOL];         // conv output (V x 800)

// ---- 1. input normalization: x = (sig - mean) / sqrt(var) ----
__global__ void k_normalize(const float* __restrict__ sig,
                            const float* __restrict__ mean,
                            const float* __restrict__ var) {
    int i = blockIdx.x * blockDim.x + threadIdx.x;
    if (i < NV * CIN) {
        int c = i % CIN;
        g_x[i] = (sig[i] - mean[c]) * rsqrtf(var[c]);
    }
}

// ---- 2. barycentric patch gather: patch[v,ra,c] = sum_j w[v,ra,j]*x[idx[v,ra,j],c]
// one warp per (v, ra) row; lanes stride over channels (coalesced on x rows)
__global__ void k_patch(const int* __restrict__ idx,
                        const float* __restrict__ w, int C) {
    int wpb = blockDim.x >> 5;
    int gw = blockIdx.x * wpb + (threadIdx.x >> 5);
    int lane = threadIdx.x & 31;
    if (gw >= NV * RA) return;
    const int*   ip = idx + (size_t)gw * 3;
    const float* wp = w   + (size_t)gw * 3;
    int   i0 = ip[0], i1 = ip[1], i2 = ip[2];
    float w0 = wp[0], w1 = wp[1], w2 = wp[2];
    float* out = g_patch + (size_t)gw * C;
    const float* x = g_x;
    for (int c = lane; c < C; c += 32)
        out[c] = w0 * x[(size_t)i0 * C + c]
               + w1 * x[(size_t)i1 * C + c]
               + w2 * x[(size_t)i2 * C + c];
}

// ---- 3. build rotated weight matrix B[k, n*T+t] = W[t, r, (a+n)%8, c],
//         k = (r*8+a)*C + c  (W input layout: (T, R, A, C) row-major)
__global__ void k_buildB(const float* __restrict__ W, int C) {
    int K = RA * C;
    int total = K * NCOL;
    int e = blockIdx.x * blockDim.x + threadIdx.x;
    if (e >= total) return;
    int k = e / NCOL, j = e % NCOL;
    int ra = k / C, c = k % C;
    int r = ra / AA, a = ra % AA;
    int n = j / TT,  t = j % TT;
    int a2 = (a + n) & (AA - 1);
    g_B[e] = W[(((size_t)t * RR + r) * AA + a2) * C + c];
}

// ---- 4. SGEMM  C = A(MxK) * B(KxN) + bias[n % biasMod], optional relu ----
// classic 128x128x8, 256 threads, 8x8 microtile
template <bool RELU>
__global__ __launch_bounds__(256)
void k_sgemm(const float* __restrict__ A, const float* __restrict__ B,
             const float* __restrict__ bias, int biasMod,
             float* __restrict__ C, int M, int N, int K) {
    const int BM = 128, BN = 128, BK = 8, TM = 8, TN = 8;
    __shared__ float As[BK][BM];
    __shared__ float Bs[BK][BN];
    int tid = threadIdx.x;
    int bm = blockIdx.y * BM, bn = blockIdx.x * BN;
    int tx = (tid & 15) * TN;   // col within tile
    int ty = (tid >> 4) * TM;   // row within tile

    float acc[TM][TN];
#pragma unroll
    for (int i = 0; i < TM; i++)
#pragma unroll
        for (int j = 0; j < TN; j++) acc[i][j] = 0.f;

    int aRow = tid >> 1;          // 0..127
    int aCol = (tid & 1) * 4;     // 0 or 4
    int bRow = tid >> 5;          // 0..7
    int bCol = (tid & 31) * 4;    // 0..124

    for (int k0 = 0; k0 < K; k0 += BK) {
#pragma unroll
        for (int i = 0; i < 4; i++) {
            int m = bm + aRow, k = k0 + aCol + i;
            As[aCol + i][aRow] = (m < M && k < K) ? A[(size_t)m * K + k] : 0.f;
        }
#pragma unroll
        for (int i = 0; i < 4; i++) {
            int k = k0 + bRow, n = bn + bCol + i;
            Bs[bRow][bCol + i] = (k < K && n < N) ? B[(size_t)k * N + n] : 0.f;
        }
        __syncthreads();
#pragma unroll
        for (int kk = 0; kk < BK; kk++) {
            float af[TM], bf[TN];
#pragma unroll
            for (int i = 0; i < TM; i++) af[i] = As[kk][ty + i];
#pragma unroll
            for (int j = 0; j < TN; j++) bf[j] = Bs[kk][tx + j];
#pragma unroll
            for (int i = 0; i < TM; i++)
#pragma unroll
                for (int j = 0; j < TN; j++) acc[i][j] = fmaf(af[i], bf[j], acc[i][j]);
        }
        __syncthreads();
    }
#pragma unroll
    for (int i = 0; i < TM; i++) {
        int m = bm + ty + i;
        if (m >= M) continue;
#pragma unroll
        for (int j = 0; j < TN; j++) {
            int n = bn + tx + j;
            if (n >= N) continue;
            float v = acc[i][j] + bias[n % biasMod];
            if (RELU) v = fmaxf(v, 0.f);
            C[(size_t)m * N + n] = v;
        }
    }
}

// ---- 5. angular max pool (by L2 norm over T) + batchnorm -> g_x (V x 100) ----
__global__ void k_amp_bn(const float* __restrict__ bn_g, const float* __restrict__ bn_b,
                         const float* __restrict__ bn_m, const float* __restrict__ bn_v,
                         int blk) {
    int v = blockIdx.x;
    __shared__ float norms[NROT];
    __shared__ int nbest;
    int tid = threadIdx.x, lane = tid & 31, w = tid >> 5;
    const float* row = g_conv + (size_t)v * NCOL;
    if (w < NROT) {
        float s = 0.f;
        for (int t = lane; t < TT; t += 32) { float x = row[w * TT + t]; s += x * x; }
#pragma unroll
        for (int o = 16; o; o >>= 1) s += __shfl_down_sync(0xffffffffu, s, o);
        if (lane == 0) norms[w] = s;
    }
    __syncthreads();
    if (tid == 0) {
        int best = 0; float bv = norms[0];
#pragma unroll
        for (int n = 1; n < NROT; n++)
            if (norms[n] > bv) { bv = norms[n]; best = n; }
        nbest = best;
    }
    __syncthreads();
    if (tid < TT) {
        float x = row[nbest * TT + tid];
        float g = bn_g[blk * TT + tid], b = bn_b[blk * TT + tid];
        float m = bn_m[blk * TT + tid], va = bn_v[blk * TT + tid];
        g_x[(size_t)v * TT + tid] = g * (x - m) * rsqrtf(va + 1e-3f) + b;
    }
}

extern "C" void kernel_launch(void* const* d_in, const int* in_sizes, int n_in,
                              void* d_out, int out_size) {
    const float* signal  = (const float*)d_in[0];
    const int*   bc_idx  = (const int*)  d_in[1];
    const float* bc_w    = (const float*)d_in[2];
    const float* nmean   = (const float*)d_in[3];
    const float* nvar    = (const float*)d_in[4];
    const float* w0      = (const float*)d_in[5];
    const float* b0      = (const float*)d_in[6];
    const float* w1      = (const float*)d_in[7];
    const float* b1      = (const float*)d_in[8];
    const float* w2      = (const float*)d_in[9];
    const float* b2      = (const float*)d_in[10];
    const float* bn_g    = (const float*)d_in[11];
    const float* bn_b    = (const float*)d_in[12];
    const float* bn_m    = (const float*)d_in[13];
    const float* bn_v    = (const float*)d_in[14];
    const float* dense_w = (const float*)d_in[15];
    const float* dense_b = (const float*)d_in[16];
    float* out = (float*)d_out;

    float *p_x, *p_patch, *p_B, *p_conv;
    cudaGetSymbolAddress((void**)&p_x, g_x);
    cudaGetSymbolAddress((void**)&p_patch, g_patch);
    cudaGetSymbolAddress((void**)&p_B, g_B);
    cudaGetSymbolAddress((void**)&p_conv, g_conv);

    // 1. normalize
    k_normalize<<<(NV * CIN + 255) / 256, 256>>>(signal, nmean, nvar);

    const float* Ws[3]   = {w0, w1, w2};
    const float* bs[3]   = {b0, b1, b2};
    const int    Cs[3]   = {CIN, TT, TT};

    int patchGrid = (NV * RA + 7) / 8;       // 8 warps per 256-thread block
    dim3 convGrid((NCOL + 127) / 128, (NV + 127) / 128);

    for (int blk = 0; blk < 3; blk++) {
        int C = Cs[blk];
        int K = RA * C;
        k_patch<<<patchGrid, 256>>>(bc_idx, bc_w, C);
        k_buildB<<<(K * NCOL + 255) / 256, 256>>>(Ws[blk], C);
        k_sgemm<true><<<convGrid, 256>>>(p_patch, p_B, bs[blk], TT,
                                         p_conv, NV, NCOL, K);
        k_amp_bn<<<NV, 256>>>(bn_g, bn_b, bn_m, bn_v, blk);
    }

    // dense head: (V x 100) @ (100 x 6890) + bias
    dim3 denseGrid((NV + 127) / 128, (NV + 127) / 128);
    k_sgemm<false><<<denseGrid, 256>>>(p_x, dense_w, dense_b, NV,
                                       out, NV, NV, TT);
}

// round 3
// speedup vs baseline: 1.3381x; 1.3381x over previous
#include <cuda_runtime.h>
#include <math.h>
#include <stdint.h>

#define NV 6890
#define CIN 3
#define RR 5
#define AA 8
#define RA 40          // RR*AA
#define NROT 8
#define TT 100
#define NCOL 800       // NROT*TT
#define KMAX (RA*TT)   // 4000

// ---- scratch (device globals; no allocation at runtime) ----
__device__ float g_x[NV * TT];                   // current features (C<=100)
__device__ float g_patch[(size_t)NV * RA * TT];  // patch matrix (V x K)
__device__ float g_B[KMAX * NCOL];               // rotated weight matrix (K x 800)
__device__ float g_conv[NV * NCOL];              // conv output (V x 800)

// split fp32 into tf32 hi + tf32 lo (3xTF32 decomposition)
__device__ __forceinline__ void tf32split(float f, uint32_t& hi, uint32_t& lo) {
    asm("cvt.rna.tf32.f32 %0, %1;" : "=r"(hi) : "f"(f));
    float r = f - __uint_as_float(hi);
    asm("cvt.rna.tf32.f32 %0, %1;" : "=r"(lo) : "f"(r));
}

// ---- 1. input normalization ----
__global__ void k_normalize(const float* __restrict__ sig,
                            const float* __restrict__ mean,
                            const float* __restrict__ var) {
    int i = blockIdx.x * blockDim.x + threadIdx.x;
    if (i < NV * CIN) {
        int c = i % CIN;
        g_x[i] = (sig[i] - mean[c]) * rsqrtf(var[c]);
    }
}

// ---- 2. barycentric patch gather ----
__global__ void k_patch(const int* __restrict__ idx,
                        const float* __restrict__ w, int C) {
    int wpb = blockDim.x >> 5;
    int gw = blockIdx.x * wpb + (threadIdx.x >> 5);
    int lane = threadIdx.x & 31;
    if (gw >= NV * RA) return;
    const int*   ip = idx + (size_t)gw * 3;
    const float* wp = w   + (size_t)gw * 3;
    int   i0 = ip[0], i1 = ip[1], i2 = ip[2];
    float w0 = wp[0], w1 = wp[1], w2 = wp[2];
    float* out = g_patch + (size_t)gw * C;
    const float* x = g_x;
    for (int c = lane; c < C; c += 32)
        out[c] = w0 * x[(size_t)i0 * C + c]
               + w1 * x[(size_t)i1 * C + c]
               + w2 * x[(size_t)i2 * C + c];
}

// ---- 3. build rotated weight matrix B[k, n*T+t] = W[t, r, (a+n)%8, c] ----
__global__ void k_buildB(const float* __restrict__ W, int C) {
    int K = RA * C;
    int total = K * NCOL;
    int e = blockIdx.x * blockDim.x + threadIdx.x;
    if (e >= total) return;
    int k = e / NCOL, j = e % NCOL;
    int ra = k / C, c = k % C;
    int r = ra / AA, a = ra % AA;
    int n = j / TT,  t = j % TT;
    int a2 = (a + n) & (AA - 1);
    g_B[e] = W[(((size_t)t * RR + r) * AA + a2) * C + c];
}

// ---- 4. 3xTF32 tensor-core GEMM: C = A(MxK) @ B(KxN) + bias, optional relu ----
// 128x128x32 block tile, 8 warps (2x4), warp tile 64x32, mma m16n8k8 tf32.
// Smem holds raw fp32; hi/lo tf32 split happens at fragment-load time.
template <bool RELU>
__global__ __launch_bounds__(256)
void k_tf32_gemm(const float* __restrict__ A, const float* __restrict__ B,
                 const float* __restrict__ bias, int biasMod,
                 float* __restrict__ C, int M, int N, int K, int vecB) {
    const int BM = 128, BN = 128, BK = 32;
    __shared__ float As[BM][BK + 4];   // row stride 36 floats
    __shared__ float Bs[BK][BN + 8];   // row stride 136 floats

    int tid = threadIdx.x;
    int bm = blockIdx.y * BM, bn = blockIdx.x * BN;
    int warp = tid >> 5, lane = tid & 31;
    int g = lane >> 2, t = lane & 3;
    int wm = (warp & 1) * 64;
    int wn = (warp >> 1) * 32;

    float acc[4][4][4];
#pragma unroll
    for (int i = 0; i < 4; i++)
#pragma unroll
        for (int j = 0; j < 4; j++)
#pragma unroll
            for (int q = 0; q < 4; q++) acc[i][j][q] = 0.f;

    for (int k0 = 0; k0 < K; k0 += BK) {
        // --- load A tile (128x32) as float4 ---
#pragma unroll
        for (int j = 0; j < 4; j++) {
            int idx = tid + 256 * j;
            int r = idx >> 3, c = (idx & 7) * 4;
            int m = bm + r, k = k0 + c;
            float4 v = make_float4(0.f, 0.f, 0.f, 0.f);
            if (m < M && k + 3 < K)
                v = *reinterpret_cast<const float4*>(A + (size_t)m * K + k);
            As[r][c + 0] = v.x; As[r][c + 1] = v.y;
            As[r][c + 2] = v.z; As[r][c + 3] = v.w;
        }
        // --- load B tile (32x128) ---
        if (vecB) {
#pragma unroll
            for (int j = 0; j < 4; j++) {
                int idx = tid + 256 * j;
                int r = idx >> 5, c = (idx & 31) * 4;
                int k = k0 + r, n = bn + c;
                float4 v = make_float4(0.f, 0.f, 0.f, 0.f);
                if (k < K && n + 3 < N)
                    v = *reinterpret_cast<const float4*>(B + (size_t)k * N + n);
                Bs[r][c + 0] = v.x; Bs[r][c + 1] = v.y;
                Bs[r][c + 2] = v.z; Bs[r][c + 3] = v.w;
            }
        } else {
#pragma unroll
            for (int j = 0; j < 16; j++) {
                int idx = tid + 256 * j;
                int r = idx >> 7, c = idx & 127;
                int k = k0 + r, n = bn + c;
                Bs[r][c] = (k < K && n < N) ? B[(size_t)k * N + n] : 0.f;
            }
        }
        __syncthreads();

#pragma unroll
        for (int ks = 0; ks < 4; ks++) {
            int kb = ks * 8;
            uint32_t ah[4][4], al[4][4], bh[4][2], bl[4][2];
#pragma unroll
            for (int mt = 0; mt < 4; mt++) {
                int mr = wm + mt * 16;
                tf32split(As[mr + g    ][kb + t    ], ah[mt][0], al[mt][0]);
                tf32split(As[mr + g + 8][kb + t    ], ah[mt][1], al[mt][1]);
                tf32split(As[mr + g    ][kb + t + 4], ah[mt][2], al[mt][2]);
                tf32split(As[mr + g + 8][kb + t + 4], ah[mt][3], al[mt][3]);
            }
#pragma unroll
            for (int nt = 0; nt < 4; nt++) {
                tf32split(Bs[kb + t    ][wn + nt * 8 + g], bh[nt][0], bl[nt][0]);
                tf32split(Bs[kb + t + 4][wn + nt * 8 + g], bh[nt][1], bl[nt][1]);
            }
#pragma unroll
            for (int mt = 0; mt < 4; mt++)
#pragma unroll
                for (int nt = 0; nt < 4; nt++) {
                    // 3xTF32: lo*hi + hi*lo + hi*hi (hi*hi last)
                    asm volatile(
                        "mma.sync.aligned.m16n8k8.row.col.f32.tf32.tf32.f32 "
                        "{%0,%1,%2,%3}, {%4,%5,%6,%7}, {%8,%9}, {%0,%1,%2,%3};"
                        : "+f"(acc[mt][nt][0]), "+f"(acc[mt][nt][1]),
                          "+f"(acc[mt][nt][2]), "+f"(acc[mt][nt][3])
                        : "r"(al[mt][0]), "r"(al[mt][1]), "r"(al[mt][2]), "r"(al[mt][3]),
                          "r"(bh[nt][0]), "r"(bh[nt][1]));
                    asm volatile(
                        "mma.sync.aligned.m16n8k8.row.col.f32.tf32.tf32.f32 "
                        "{%0,%1,%2,%3}, {%4,%5,%6,%7}, {%8,%9}, {%0,%1,%2,%3};"
                        : "+f"(acc[mt][nt][0]), "+f"(acc[mt][nt][1]),
                          "+f"(acc[mt][nt][2]), "+f"(acc[mt][nt][3])
                        : "r"(ah[mt][0]), "r"(ah[mt][1]), "r"(ah[mt][2]), "r"(ah[mt][3]),
                          "r"(bl[nt][0]), "r"(bl[nt][1]));
                    asm volatile(
                        "mma.sync.aligned.m16n8k8.row.col.f32.tf32.tf32.f32 "
                        "{%0,%1,%2,%3}, {%4,%5,%6,%7}, {%8,%9}, {%0,%1,%2,%3};"
                        : "+f"(acc[mt][nt][0]), "+f"(acc[mt][nt][1]),
                          "+f"(acc[mt][nt][2]), "+f"(acc[mt][nt][3])
                        : "r"(ah[mt][0]), "r"(ah[mt][1]), "r"(ah[mt][2]), "r"(ah[mt][3]),
                          "r"(bh[nt][0]), "r"(bh[nt][1]));
                }
        }
        __syncthreads();
    }

    // --- epilogue: bias + relu + guarded stores ---
#pragma unroll
    for (int mt = 0; mt < 4; mt++) {
#pragma unroll
        for (int nt = 0; nt < 4; nt++) {
            int row = bm + wm + mt * 16 + g;
            int col = bn + wn + nt * 8 + 2 * t;
#pragma unroll
            for (int h = 0; h < 2; h++) {
                int r = row + h * 8;
                if (r >= M) continue;
#pragma unroll
                for (int q = 0; q < 2; q++) {
                    int n = col + q;
                    if (n >= N) continue;
                    float v = acc[mt][nt][h * 2 + q] + bias[n % biasMod];
                    if (RELU) v = fmaxf(v, 0.f);
                    C[(size_t)r * N + n] = v;
                }
            }
        }
    }
}

// ---- 5. angular max pool (by L2 norm over T) + batchnorm -> g_x (V x 100) ----
__global__ void k_amp_bn(const float* __restrict__ bn_g, const float* __restrict__ bn_b,
                         const float* __restrict__ bn_m, const float* __restrict__ bn_v,
                         int blk) {
    int v = blockIdx.x;
    __shared__ float norms[NROT];
    __shared__ int nbest;
    int tid = threadIdx.x, lane = tid & 31, w = tid >> 5;
    const float* row = g_conv + (size_t)v * NCOL;
    if (w < NROT) {
        float s = 0.f;
        for (int t = lane; t < TT; t += 32) { float x = row[w * TT + t]; s += x * x; }
#pragma unroll
        for (int o = 16; o; o >>= 1) s += __shfl_down_sync(0xffffffffu, s, o);
        if (lane == 0) norms[w] = s;
    }
    __syncthreads();
    if (tid == 0) {
        int best = 0; float bv = norms[0];
#pragma unroll
        for (int n = 1; n < NROT; n++)
            if (norms[n] > bv) { bv = norms[n]; best = n; }
        nbest = best;
    }
    __syncthreads();
    if (tid < TT) {
        float x = row[nbest * TT + tid];
        float gg = bn_g[blk * TT + tid], bb = bn_b[blk * TT + tid];
        float mm = bn_m[blk * TT + tid], va = bn_v[blk * TT + tid];
        g_x[(size_t)v * TT + tid] = gg * (x - mm) * rsqrtf(va + 1e-3f) + bb;
    }
}

extern "C" void kernel_launch(void* const* d_in, const int* in_sizes, int n_in,
                              void* d_out, int out_size) {
    const float* signal  = (const float*)d_in[0];
    const int*   bc_idx  = (const int*)  d_in[1];
    const float* bc_w    = (const float*)d_in[2];
    const float* nmean   = (const float*)d_in[3];
    const float* nvar    = (const float*)d_in[4];
    const float* w0      = (const float*)d_in[5];
    const float* b0      = (const float*)d_in[6];
    const float* w1      = (const float*)d_in[7];
    const float* b1      = (const float*)d_in[8];
    const float* w2      = (const float*)d_in[9];
    const float* b2      = (const float*)d_in[10];
    const float* bn_g    = (const float*)d_in[11];
    const float* bn_b    = (const float*)d_in[12];
    const float* bn_m    = (const float*)d_in[13];
    const float* bn_v    = (const float*)d_in[14];
    const float* dense_w = (const float*)d_in[15];
    const float* dense_b = (const float*)d_in[16];
    float* out = (float*)d_out;

    float *p_x, *p_patch, *p_B, *p_conv;
    cudaGetSymbolAddress((void**)&p_x, g_x);
    cudaGetSymbolAddress((void**)&p_patch, g_patch);
    cudaGetSymbolAddress((void**)&p_B, g_B);
    cudaGetSymbolAddress((void**)&p_conv, g_conv);

    k_normalize<<<(NV * CIN + 255) / 256, 256>>>(signal, nmean, nvar);

    const float* Ws[3] = {w0, w1, w2};
    const float* bs[3] = {b0, b1, b2};
    const int    Cs[3] = {CIN, TT, TT};

    int patchGrid = (NV * RA + 7) / 8;
    dim3 convGrid((NCOL + 127) / 128, (NV + 127) / 128);

    for (int blk = 0; blk < 3; blk++) {
        int C = Cs[blk];
        int K = RA * C;
        k_patch<<<patchGrid, 256>>>(bc_idx, bc_w, C);
        k_buildB<<<(K * NCOL + 255) / 256, 256>>>(Ws[blk], C);
        k_tf32_gemm<true><<<convGrid, 256>>>(p_patch, p_B, bs[blk], TT,
                                             p_conv, NV, NCOL, K, /*vecB=*/1);
        k_amp_bn<<<NV, 256>>>(bn_g, bn_b, bn_m, bn_v, blk);
    }

    // dense head: (V x 100) @ (100 x 6890) + bias  (N=6890 not /4 -> scalar B path)
    dim3 denseGrid((NV + 127) / 128, (NV + 127) / 128);
    k_tf32_gemm<false><<<denseGrid, 256>>>(p_x, dense_w, dense_b, NV,
                                           out, NV, NV, TT, /*vecB=*/0);
}

// round 4
// speedup vs baseline: 2.9648x; 2.2157x over previous
#include <cuda_runtime.h>
#include <cuda_bf16.h>
#include <math.h>
#include <stdint.h>

#define NV 6890
#define MP 6912            // padded M (multiple of 128)
#define CIN 3
#define RR 5
#define AA 8
#define RA 40
#define TT 100
#define NCOL 800
#define LDA 12096          // conv A' row stride (>= 12032)
#define LDBC 896           // conv B' row stride (7*128)
#define LDAX 320           // dense A' row stride
#define LDBD 6912          // dense B' row stride (54*128)
#define KT_CONV1 384       // 3*120 padded to 64
#define KT_CONV23 12032    // 3*4000 padded to 64
#define KT_DENSE 320       // 3*100 padded to 64

// ---- scratch (device globals, zero-initialized at module load) ----
__device__ float g_x[NV * TT];
__device__ __nv_bfloat16 g_A [(size_t)MP * LDA];        // tripled bf16 patch
__device__ __nv_bfloat16 g_B [(size_t)12096 * LDBC];    // tripled bf16 rotated weights
__device__ __nv_bfloat16 g_Ax[(size_t)MP * LDAX];       // tripled bf16 dense input
__device__ __nv_bfloat16 g_Bd[(size_t)KT_DENSE * LDBD]; // tripled bf16 dense weights
__device__ float g_conv[NV * NCOL];

__device__ __forceinline__ void bfsplit(float f, __nv_bfloat16& hi, __nv_bfloat16& lo) {
    hi = __float2bfloat16(f);
    lo = __float2bfloat16(f - __bfloat162float(hi));
}

__device__ __forceinline__ uint32_t sptr(const void* p) {
    return (uint32_t)__cvta_generic_to_shared(p);
}

// ---- 1. input normalization ----
__global__ void k_normalize(const float* __restrict__ sig,
                            const float* __restrict__ mean,
                            const float* __restrict__ var) {
    int i = blockIdx.x * blockDim.x + threadIdx.x;
    if (i < NV * CIN) {
        int c = i % CIN;
        g_x[i] = (sig[i] - mean[c]) * rsqrtf(var[c]);
    }
}

// ---- 2. barycentric patch gather -> tripled bf16 A' (slots [hi, hi, lo]) ----
__global__ void k_patch(const int* __restrict__ idx,
                        const float* __restrict__ w, int C, int KT) {
    int gw = blockIdx.x * 8 + (threadIdx.x >> 5);
    int lane = threadIdx.x & 31;
    if (gw >= NV * RA) return;
    int v = gw / RA, ra = gw % RA;
    const int*   ip = idx + (size_t)gw * 3;
    const float* wp = w   + (size_t)gw * 3;
    int   i0 = ip[0], i1 = ip[1], i2 = ip[2];
    float w0 = wp[0], w1 = wp[1], w2 = wp[2];
    __nv_bfloat16* row = g_A + (size_t)v * LDA;
    for (int c = lane; c < C; c += 32) {
        float p = w0 * g_x[i0 * C + c] + w1 * g_x[i1 * C + c] + w2 * g_x[i2 * C + c];
        __nv_bfloat16 hi, lo; bfsplit(p, hi, lo);
        int kb = 3 * (ra * C + c);
        row[kb] = hi; row[kb + 1] = hi; row[kb + 2] = lo;
    }
    if (ra == 0) {  // zero the K padding (buffer reused across layers with different K)
        __nv_bfloat16 z = __float2bfloat16(0.f);
        for (int e = 3 * RA * C + lane; e < KT; e += 32) row[e] = z;
    }
}

// ---- 3. rotated weights -> tripled bf16 B' (slots [hi, lo, hi]) ----
__global__ void k_buildB(const float* __restrict__ W, int C, int KT) {
    int K = RA * C;
    int total = K * NCOL;
    int e = blockIdx.x * blockDim.x + threadIdx.x;
    if (e < total) {
        int k = e / NCOL, n = e % NCOL;
        int ra = k / C, c = k % C;
        int r = ra / AA, a = ra % AA;
        int rot = n / TT;
        int t = n - rot * TT;
        int a2 = (a + rot) & 7;
        float val = W[(((size_t)t * RR + r) * AA + a2) * C + c];
        __nv_bfloat16 hi, lo; bfsplit(val, hi, lo);
        size_t o = (size_t)(3 * k) * LDBC + n;
        g_B[o] = hi; g_B[o + LDBC] = lo; g_B[o + 2 * LDBC] = hi;
    }
    // zero pad rows [3K, KT) (buffer reused across layers)
    int padElems = (KT - 3 * K) * LDBC;
    __nv_bfloat16 z = __float2bfloat16(0.f);
    for (int p = e; p < padElems; p += gridDim.x * blockDim.x)
        g_B[(size_t)(3 * K) * LDBC + p] = z;
}

// ---- 3b. dense weights -> tripled bf16 B' ----
__global__ void k_buildDense(const float* __restrict__ dw) {
    int e = blockIdx.x * blockDim.x + threadIdx.x;
    if (e >= TT * NV) return;
    int k = e / NV, n = e % NV;
    float val = dw[e];
    __nv_bfloat16 hi, lo; bfsplit(val, hi, lo);
    size_t o = (size_t)(3 * k) * LDBD + n;
    g_Bd[o] = hi; g_Bd[o + LDBD] = lo; g_Bd[o + 2 * LDBD] = hi;
}

// ---- 4. bf16x3 tensor-core GEMM: C = A'(M x KT) @ B'(KT x N) + bias ----
// 128x128x64 tile, 3-stage cp.async, ldmatrix fragments, mma m16n8k16 bf16.
template <bool RELU>
__global__ void __launch_bounds__(256, 2)
k_gemm(const __nv_bfloat16* __restrict__ A, int lda,
       const __nv_bfloat16* __restrict__ B, int ldb,
       const float* __restrict__ bias, int biasMod,
       float* __restrict__ C, int ldc, int M, int N, int KT) {
    extern __shared__ char smem[];
    const int STAGE = 32768;  // As 16KB + Bs 16KB
    int tid = threadIdx.x;
    int bm = blockIdx.y * 128, bn = blockIdx.x * 128;
    int warp = tid >> 5, lane = tid & 31;
    int wm = (warp & 1) * 64, wn = (warp >> 1) * 32;

    float acc[4][4][4];
#pragma unroll
    for (int i = 0; i < 4; i++)
#pragma unroll
        for (int j = 0; j < 4; j++)
#pragma unroll
            for (int q = 0; q < 4; q++) acc[i][j][q] = 0.f;

    // ---- async copy helpers (swizzled: 16B unit u of row r goes to u ^ (r&7)) ----
    auto copyA = [&](int stage, int k0) {
        int r = tid >> 1, ub = (tid & 1) * 4;
        const __nv_bfloat16* src = A + (size_t)(bm + r) * lda + k0;
        char* dst = smem + stage * STAGE + r * 128;
#pragma unroll
        for (int i = 0; i < 4; i++) {
            int uu = ub + i, su = uu ^ (r & 7);
            uint32_t d = sptr(dst + su * 16);
            asm volatile("cp.async.cg.shared.global [%0], [%1], 16;"
                         :: "r"(d), "l"(src + uu * 8));
        }
    };
    auto copyB = [&](int stage, int k0) {
        int r = tid >> 2, ub = (tid & 3) * 4;
        const __nv_bfloat16* src = B + (size_t)(k0 + r) * ldb + bn;
        char* dst = smem + stage * STAGE + 16384 + r * 256;
#pragma unroll
        for (int i = 0; i < 4; i++) {
            int uu = ub + i, su = (uu & 8) | ((uu ^ r) & 7);
            uint32_t d = sptr(dst + su * 16);
            asm volatile("cp.async.cg.shared.global [%0], [%1], 16;"
                         :: "r"(d), "l"(src + uu * 8));
        }
    };

    int niter = KT >> 6;
    copyA(0, 0);  copyB(0, 0);
    asm volatile("cp.async.commit_group;");
    copyA(1, 64); copyB(1, 64);
    asm volatile("cp.async.commit_group;");

    int q = lane >> 3, rr = lane & 7;

    for (int i = 0; i < niter; i++) {
        int pf = i + 2;
        if (pf < niter) {
            int st = pf % 3;
            copyA(st, pf * 64); copyB(st, pf * 64);
        }
        asm volatile("cp.async.commit_group;");
        asm volatile("cp.async.wait_group 2;");
        __syncthreads();

        int st = i % 3;
        const char* sA = smem + st * STAGE;
        const char* sB = smem + st * STAGE + 16384;
#pragma unroll
        for (int ks = 0; ks < 4; ks++) {
            uint32_t a[4][4], bfr[4][2];
#pragma unroll
            for (int mt = 0; mt < 4; mt++) {
                int m_loc = wm + mt * 16 + (q & 1) * 8 + rr;
                int unit = ks * 2 + (q >> 1);
                int su = unit ^ (m_loc & 7);
                uint32_t ad = sptr(sA + m_loc * 128 + su * 16);
                asm volatile("ldmatrix.sync.aligned.m8n8.x4.shared.b16 {%0,%1,%2,%3}, [%4];"
                             : "=r"(a[mt][0]), "=r"(a[mt][1]), "=r"(a[mt][2]), "=r"(a[mt][3])
                             : "r"(ad));
            }
#pragma unroll
            for (int ntp = 0; ntp < 2; ntp++) {
                int k_loc = ks * 16 + (q & 1) * 8 + rr;
                int unit = (wn >> 3) + ntp * 2 + (q >> 1);
                int su = (unit & 8) | ((unit ^ k_loc) & 7);
                uint32_t ad = sptr(sB + k_loc * 256 + su * 16);
                asm volatile("ldmatrix.sync.aligned.m8n8.x4.trans.shared.b16 {%0,%1,%2,%3}, [%4];"
                             : "=r"(bfr[2 * ntp][0]), "=r"(bfr[2 * ntp][1]),
                               "=r"(bfr[2 * ntp + 1][0]), "=r"(bfr[2 * ntp + 1][1])
                             : "r"(ad));
            }
#pragma unroll
            for (int mt = 0; mt < 4; mt++)
#pragma unroll
                for (int nt = 0; nt < 4; nt++) {
                    asm volatile(
                        "mma.sync.aligned.m16n8k16.row.col.f32.bf16.bf16.f32 "
                        "{%0,%1,%2,%3}, {%4,%5,%6,%7}, {%8,%9}, {%0,%1,%2,%3};"
                        : "+f"(acc[mt][nt][0]), "+f"(acc[mt][nt][1]),
                          "+f"(acc[mt][nt][2]), "+f"(acc[mt][nt][3])
                        : "r"(a[mt][0]), "r"(a[mt][1]), "r"(a[mt][2]), "r"(a[mt][3]),
                          "r"(bfr[nt][0]), "r"(bfr[nt][1]));
                }
        }
        __syncthreads();
    }

    // ---- epilogue ----
    int g = lane >> 2, t4 = lane & 3;
#pragma unroll
    for (int mt = 0; mt < 4; mt++) {
#pragma unroll
        for (int nt = 0; nt < 4; nt++) {
            int row0 = bm + wm + mt * 16 + g;
            int col0 = bn + wn + nt * 8 + 2 * t4;
#pragma unroll
            for (int h = 0; h < 2; h++) {
                int r = row0 + h * 8;
                if (r >= M) continue;
#pragma unroll
                for (int qq = 0; qq < 2; qq++) {
                    int n = col0 + qq;
                    if (n >= N) continue;
                    float v = acc[mt][nt][h * 2 + qq] + bias[n % biasMod];
                    if (RELU) v = fmaxf(v, 0.f);
                    C[(size_t)r * ldc + n] = v;
                }
            }
        }
    }
}

// ---- 5. angular max pool + batchnorm -> g_x (fp32) and g_Ax (tripled bf16) ----
__global__ void k_amp_bn(const float* __restrict__ bn_g, const float* __restrict__ bn_b,
                         const float* __restrict__ bn_m, const float* __restrict__ bn_v,
                         int blk) {
    int v = blockIdx.x;
    __shared__ float norms[8];
    __shared__ int nbest;
    int tid = threadIdx.x, lane = tid & 31, w = tid >> 5;
    const float* row = g_conv + (size_t)v * NCOL;
    if (w < 8) {
        float s = 0.f;
        for (int t = lane; t < TT; t += 32) { float x = row[w * TT + t]; s += x * x; }
#pragma unroll
        for (int o = 16; o; o >>= 1) s += __shfl_down_sync(0xffffffffu, s, o);
        if (lane == 0) norms[w] = s;
    }
    __syncthreads();
    if (tid == 0) {
        int best = 0; float bv = norms[0];
#pragma unroll
        for (int n = 1; n < 8; n++)
            if (norms[n] > bv) { bv = norms[n]; best = n; }
        nbest = best;
    }
    __syncthreads();
    if (tid < TT) {
        float x = row[nbest * TT + tid];
        float gg = bn_g[blk * TT + tid], bb = bn_b[blk * TT + tid];
        float mm = bn_m[blk * TT + tid], va = bn_v[blk * TT + tid];
        float y = gg * (x - mm) * rsqrtf(va + 1e-3f) + bb;
        g_x[(size_t)v * TT + tid] = y;
        __nv_bfloat16 hi, lo; bfsplit(y, hi, lo);
        __nv_bfloat16* arow = g_Ax + (size_t)v * LDAX;
        arow[3 * tid] = hi; arow[3 * tid + 1] = hi; arow[3 * tid + 2] = lo;
    }
}

extern "C" void kernel_launch(void* const* d_in, const int* in_sizes, int n_in,
                              void* d_out, int out_size) {
    const float* signal  = (const float*)d_in[0];
    const int*   bc_idx  = (const int*)  d_in[1];
    const float* bc_w    = (const float*)d_in[2];
    const float* nmean   = (const float*)d_in[3];
    const float* nvar    = (const float*)d_in[4];
    const float* w0      = (const float*)d_in[5];
    const float* b0      = (const float*)d_in[6];
    const float* w1      = (const float*)d_in[7];
    const float* b1      = (const float*)d_in[8];
    const float* w2      = (const float*)d_in[9];
    const float* b2      = (const float*)d_in[10];
    const float* bn_g    = (const float*)d_in[11];
    const float* bn_b    = (const float*)d_in[12];
    const float* bn_m    = (const float*)d_in[13];
    const float* bn_v    = (const float*)d_in[14];
    const float* dense_w = (const float*)d_in[15];
    const float* dense_b = (const float*)d_in[16];
    float* out = (float*)d_out;

    const int SMEM = 3 * 32768;
    cudaFuncSetAttribute(k_gemm<true>,  cudaFuncAttributeMaxDynamicSharedMemorySize, SMEM);
    cudaFuncSetAttribute(k_gemm<false>, cudaFuncAttributeMaxDynamicSharedMemorySize, SMEM);

    __nv_bfloat16 *p_A, *p_B, *p_Ax, *p_Bd;
    float *p_conv;
    cudaGetSymbolAddress((void**)&p_A, g_A);
    cudaGetSymbolAddress((void**)&p_B, g_B);
    cudaGetSymbolAddress((void**)&p_Ax, g_Ax);
    cudaGetSymbolAddress((void**)&p_Bd, g_Bd);
    cudaGetSymbolAddress((void**)&p_conv, g_conv);

    k_normalize<<<(NV * CIN + 255) / 256, 256>>>(signal, nmean, nvar);

    const float* Ws[3] = {w0, w1, w2};
    const float* bs[3] = {b0, b1, b2};
    const int    Cs[3] = {CIN, TT, TT};
    const int    KTs[3] = {KT_CONV1, KT_CONV23, KT_CONV23};

    int patchGrid = (NV * RA + 7) / 8;
    dim3 convGrid(7, 54);   // N=800 -> 7 tiles, M=6890 -> 54 tiles

    for (int blk = 0; blk < 3; blk++) {
        int C = Cs[blk];
        int K = RA * C;
        k_patch<<<patchGrid, 256>>>(bc_idx, bc_w, C, KTs[blk]);
        k_buildB<<<(K * NCOL + 255) / 256, 256>>>(Ws[blk], C, KTs[blk]);
        k_gemm<true><<<convGrid, 256, SMEM>>>(p_A, LDA, p_B, LDBC, bs[blk], TT,
                                              p_conv, NCOL, NV, NCOL, KTs[blk]);
        k_amp_bn<<<NV, 256>>>(bn_g, bn_b, bn_m, bn_v, blk);
    }

    // dense head
    k_buildDense<<<(TT * NV + 255) / 256, 256>>>(dense_w);
    dim3 denseGrid(54, 54);
    k_gemm<false><<<denseGrid, 256, SMEM>>>(p_Ax, LDAX, p_Bd, LDBD, dense_b, NV,
                                            out, NV, NV, NV, KT_DENSE);
}

// round 6
// speedup vs baseline: 3.2683x; 1.1023x over previous
#include <cuda_runtime.h>
#include <cuda_bf16.h>
#include <math.h>
#include <stdint.h>

#define NV 6890
#define MP 6912            // padded M (multiple of 128)
#define CIN 3
#define RR 5
#define AA 8
#define RA 40
#define TT 100
#define NCOL 800
#define LDA 12096          // conv A' row stride (>= 12032)
#define LDBC 896           // conv B' row stride (7*128)
#define LDAX 320           // dense A' row stride
#define LDBD 6912          // dense B' row stride (54*128)
#define KT_CONV1 384       // 3*120 padded to 64
#define KT_CONV23 12032    // 3*4000 padded to 64
#define KT_DENSE 320       // 3*100 padded to 64

// ---- scratch (device globals, zero-initialized at module load; pads stay zero) ----
__device__ float g_x[NV * TT];
__device__ __nv_bfloat16 g_A [(size_t)MP * LDA];        // tripled bf16 patch [hi,hi,lo]
__device__ __nv_bfloat16 g_B [(size_t)12096 * LDBC];    // tripled bf16 rotated weights [hi,lo,hi]
__device__ __nv_bfloat16 g_Ax[(size_t)MP * LDAX];       // tripled bf16 dense input
__device__ __nv_bfloat16 g_Bd[(size_t)KT_DENSE * LDBD]; // tripled bf16 dense weights
__device__ float g_conv[NV * NCOL];

__device__ __forceinline__ void bfsplit(float f, __nv_bfloat16& hi, __nv_bfloat16& lo) {
    hi = __float2bfloat16(f);
    lo = __float2bfloat16(f - __bfloat162float(hi));
}

__device__ __forceinline__ uint32_t sptr(const void* p) {
    return (uint32_t)__cvta_generic_to_shared(p);
}

// ---- 1. input normalization ----
__global__ void k_normalize(const float* __restrict__ sig,
                            const float* __restrict__ mean,
                            const float* __restrict__ var) {
    int i = blockIdx.x * blockDim.x + threadIdx.x;
    if (i < NV * CIN) {
        int c = i % CIN;
        g_x[i] = (sig[i] - mean[c]) * rsqrtf(var[c]);
    }
}

// ---- 2. barycentric patch gather -> tripled bf16 A' (slots [hi, hi, lo]) ----
__global__ void k_patch(const int* __restrict__ idx,
                        const float* __restrict__ w, int C, int KT) {
    int gw = blockIdx.x * 8 + (threadIdx.x >> 5);
    int lane = threadIdx.x & 31;
    if (gw >= NV * RA) return;
    int v = gw / RA, ra = gw % RA;
    const int*   ip = idx + (size_t)gw * 3;
    const float* wp = w   + (size_t)gw * 3;
    int   i0 = ip[0], i1 = ip[1], i2 = ip[2];
    float w0 = wp[0], w1 = wp[1], w2 = wp[2];
    __nv_bfloat16* row = g_A + (size_t)v * LDA;
    for (int c = lane; c < C; c += 32) {
        float p = w0 * g_x[i0 * C + c] + w1 * g_x[i1 * C + c] + w2 * g_x[i2 * C + c];
        __nv_bfloat16 hi, lo; bfsplit(p, hi, lo);
        int kb = 3 * (ra * C + c);
        row[kb] = hi; row[kb + 1] = hi; row[kb + 2] = lo;
    }
    if (ra == 0) {  // zero K padding (rewritten every launch -> deterministic)
        __nv_bfloat16 z = __float2bfloat16(0.f);
        for (int e = 3 * RA * C + lane; e < KT; e += 32) row[e] = z;
    }
}

// ---- 3. rotated weights -> tripled bf16 B' ([K'][N] layout, slots [hi,lo,hi]) ----
__global__ void k_buildB(const float* __restrict__ W, int C, int KT) {
    int K = RA * C;
    int total = K * NCOL;
    int e = blockIdx.x * blockDim.x + threadIdx.x;
    if (e < total) {
        int k = e / NCOL, n = e % NCOL;
        int ra = k / C, c = k % C;
        int r = ra / AA, a = ra % AA;
        int rot = n / TT;
        int t = n - rot * TT;
        int a2 = (a + rot) & 7;
        float val = W[(((size_t)t * RR + r) * AA + a2) * C + c];
        __nv_bfloat16 hi, lo; bfsplit(val, hi, lo);
        size_t o = (size_t)(3 * k) * LDBC + n;
        g_B[o] = hi; g_B[o + LDBC] = lo; g_B[o + 2 * LDBC] = hi;
    }
    // zero pad rows [3K, KT)
    int padElems = (KT - 3 * K) * LDBC;
    __nv_bfloat16 z = __float2bfloat16(0.f);
    for (int p = e; p < padElems; p += gridDim.x * blockDim.x)
        g_B[(size_t)(3 * K) * LDBC + p] = z;
}

// ---- 3b. dense weights -> tripled bf16 B' ----
__global__ void k_buildDense(const float* __restrict__ dw) {
    int e = blockIdx.x * blockDim.x + threadIdx.x;
    if (e >= TT * NV) return;
    int k = e / NV, n = e % NV;
    float val = dw[e];
    __nv_bfloat16 hi, lo; bfsplit(val, hi, lo);
    size_t o = (size_t)(3 * k) * LDBD + n;
    g_Bd[o] = hi; g_Bd[o + LDBD] = lo; g_Bd[o + 2 * LDBD] = hi;
}

// ---- 4. bf16x3 tensor-core GEMM: C = A'(M x KT) @ B'(KT x N) + bias ----
// 128x128x64 tile, 3-stage cp.async ring, ONE __syncthreads per chunk
// (order: wait -> sync -> issue prefetch -> compute), mma m16n8k16 bf16.
template <bool RELU>
__global__ void __launch_bounds__(256, 2)
k_gemm(const __nv_bfloat16* __restrict__ A, int lda,
       const __nv_bfloat16* __restrict__ B, int ldb,
       const float* __restrict__ bias, int biasMod,
       float* __restrict__ C, int ldc, int M, int N, int KT) {
    extern __shared__ char smem[];
    __shared__ float sbias[128];
    const int STAGE = 32768;  // As 16KB + Bs 16KB
    int tid = threadIdx.x;
    int bm = blockIdx.y * 128, bn = blockIdx.x * 128;
    int warp = tid >> 5, lane = tid & 31;
    int wm = (warp & 1) * 64, wn = (warp >> 1) * 32;

    if (tid < 128) sbias[tid] = bias[(bn + tid) % biasMod];

    float acc[4][4][4];
#pragma unroll
    for (int i = 0; i < 4; i++)
#pragma unroll
        for (int j = 0; j < 4; j++)
#pragma unroll
            for (int q = 0; q < 4; q++) acc[i][j][q] = 0.f;

    // ---- async copy helpers (swizzled: 16B unit u of row r goes to u ^ (r&7)) ----
    auto copyA = [&](int stage, int k0) {
        int r = tid >> 1, ub = (tid & 1) * 4;
        const __nv_bfloat16* src = A + (size_t)(bm + r) * lda + k0;
        char* dst = smem + stage * STAGE + r * 128;
#pragma unroll
        for (int i = 0; i < 4; i++) {
            int uu = ub + i, su = uu ^ (r & 7);
            uint32_t d = sptr(dst + su * 16);
            asm volatile("cp.async.cg.shared.global [%0], [%1], 16;"
                         :: "r"(d), "l"(src + uu * 8));
        }
    };
    auto copyB = [&](int stage, int k0) {
        int r = tid >> 2, ub = (tid & 3) * 4;
        const __nv_bfloat16* src = B + (size_t)(k0 + r) * ldb + bn;
        char* dst = smem + stage * STAGE + 16384 + r * 256;
#pragma unroll
        for (int i = 0; i < 4; i++) {
            int uu = ub + i, su = (uu & 8) | ((uu ^ r) & 7);
            uint32_t d = sptr(dst + su * 16);
            asm volatile("cp.async.cg.shared.global [%0], [%1], 16;"
                         :: "r"(d), "l"(src + uu * 8));
        }
    };

    int niter = KT >> 6;
    // prologue: chunks 0,1 -> stages 0,1
    copyA(0, 0);  copyB(0, 0);
    asm volatile("cp.async.commit_group;");
    copyA(1, 64); copyB(1, 64);
    asm volatile("cp.async.commit_group;");

    int q = lane >> 3, rr = lane & 7;

    for (int i = 0; i < niter; i++) {
        // chunk i resident once all but the newest group are done
        asm volatile("cp.async.wait_group 1;");
        __syncthreads();                 // also fences prior iter's reads of stage (i+2)%3

        int pf = i + 2;
        if (pf < niter) {
            int st2 = pf % 3;
            copyA(st2, pf * 64); copyB(st2, pf * 64);
        }
        asm volatile("cp.async.commit_group;");   // commit every iter (possibly empty)

        int st = i % 3;
        const char* sA = smem + st * STAGE;
        const char* sB = smem + st * STAGE + 16384;
#pragma unroll
        for (int ks = 0; ks < 4; ks++) {
            uint32_t a[4][4], bfr[4][2];
#pragma unroll
            for (int mt = 0; mt < 4; mt++) {
                int m_loc = wm + mt * 16 + (q & 1) * 8 + rr;
                int unit = ks * 2 + (q >> 1);
                int su = unit ^ (m_loc & 7);
                uint32_t ad = sptr(sA + m_loc * 128 + su * 16);
                asm volatile("ldmatrix.sync.aligned.m8n8.x4.shared.b16 {%0,%1,%2,%3}, [%4];"
                             : "=r"(a[mt][0]), "=r"(a[mt][1]), "=r"(a[mt][2]), "=r"(a[mt][3])
                             : "r"(ad));
            }
#pragma unroll
            for (int ntp = 0; ntp < 2; ntp++) {
                int k_loc = ks * 16 + (q & 1) * 8 + rr;
                int unit = (wn >> 3) + ntp * 2 + (q >> 1);
                int su = (unit & 8) | ((unit ^ k_loc) & 7);
                uint32_t ad = sptr(sB + k_loc * 256 + su * 16);
                asm volatile("ldmatrix.sync.aligned.m8n8.x4.trans.shared.b16 {%0,%1,%2,%3}, [%4];"
                             : "=r"(bfr[2 * ntp][0]), "=r"(bfr[2 * ntp][1]),
                               "=r"(bfr[2 * ntp + 1][0]), "=r"(bfr[2 * ntp + 1][1])
                             : "r"(ad));
            }
#pragma unroll
            for (int mt = 0; mt < 4; mt++)
#pragma unroll
                for (int nt = 0; nt < 4; nt++) {
                    asm volatile(
                        "mma.sync.aligned.m16n8k16.row.col.f32.bf16.bf16.f32 "
                        "{%0,%1,%2,%3}, {%4,%5,%6,%7}, {%8,%9}, {%0,%1,%2,%3};"
                        : "+f"(acc[mt][nt][0]), "+f"(acc[mt][nt][1]),
                          "+f"(acc[mt][nt][2]), "+f"(acc[mt][nt][3])
                        : "r"(a[mt][0]), "r"(a[mt][1]), "r"(a[mt][2]), "r"(a[mt][3]),
                          "r"(bfr[nt][0]), "r"(bfr[nt][1]));
                }
        }
    }

    // ---- epilogue: bias from smem, float2 stores (N even -> pair-aligned) ----
    int g = lane >> 2, t4 = lane & 3;
#pragma unroll
    for (int mt = 0; mt < 4; mt++) {
#pragma unroll
        for (int nt = 0; nt < 4; nt++) {
            int lcol = wn + nt * 8 + 2 * t4;
            int col = bn + lcol;
            if (col >= N) continue;
            float b0 = sbias[lcol], b1 = sbias[lcol + 1];
            int row0 = bm + wm + mt * 16 + g;
#pragma unroll
            for (int h = 0; h < 2; h++) {
                int r = row0 + h * 8;
                if (r >= M) continue;
                float v0 = acc[mt][nt][h * 2 + 0] + b0;
                float v1 = acc[mt][nt][h * 2 + 1] + b1;
                if (RELU) { v0 = fmaxf(v0, 0.f); v1 = fmaxf(v1, 0.f); }
                *reinterpret_cast<float2*>(C + (size_t)r * ldc + col) = make_float2(v0, v1);
            }
        }
    }
}

// ---- 5. angular max pool + batchnorm -> g_x (fp32) and g_Ax (tripled bf16) ----
__global__ void k_amp_bn(const float* __restrict__ bn_g, const float* __restrict__ bn_b,
                         const float* __restrict__ bn_m, const float* __restrict__ bn_v,
                         int blk) {
    int v = blockIdx.x;
    __shared__ float norms[8];
    __shared__ int nbest;
    int tid = threadIdx.x, lane = tid & 31, w = tid >> 5;
    const float* row = g_conv + (size_t)v * NCOL;
    if (w < 8) {
        float s = 0.f;
        for (int t = lane; t < TT; t += 32) { float x = row[w * TT + t]; s += x * x; }
#pragma unroll
        for (int o = 16; o; o >>= 1) s += __shfl_down_sync(0xffffffffu, s, o);
        if (lane == 0) norms[w] = s;
    }
    __syncthreads();
    if (tid == 0) {
        int best = 0; float bv = norms[0];
#pragma unroll
        for (int n = 1; n < 8; n++)
            if (norms[n] > bv) { bv = norms[n]; best = n; }
        nbest = best;
    }
    __syncthreads();
    if (tid < TT) {
        float x = row[nbest * TT + tid];
        float gg = bn_g[blk * TT + tid], bb = bn_b[blk * TT + tid];
        float mm = bn_m[blk * TT + tid], va = bn_v[blk * TT + tid];
        float y = gg * (x - mm) * rsqrtf(va + 1e-3f) + bb;
        g_x[(size_t)v * TT + tid] = y;
        __nv_bfloat16 hi, lo; bfsplit(y, hi, lo);
        __nv_bfloat16* arow = g_Ax + (size_t)v * LDAX;
        arow[3 * tid] = hi; arow[3 * tid + 1] = hi; arow[3 * tid + 2] = lo;
    }
}

extern "C" void kernel_launch(void* const* d_in, const int* in_sizes, int n_in,
                              void* d_out, int out_size) {
    const float* signal  = (const float*)d_in[0];
    const int*   bc_idx  = (const int*)  d_in[1];
    const float* bc_w    = (const float*)d_in[2];
    const float* nmean   = (const float*)d_in[3];
    const float* nvar    = (const float*)d_in[4];
    const float* w0      = (const float*)d_in[5];
    const float* b0      = (const float*)d_in[6];
    const float* w1      = (const float*)d_in[7];
    const float* b1      = (const float*)d_in[8];
    const float* w2      = (const float*)d_in[9];
    const float* b2      = (const float*)d_in[10];
    const float* bn_g    = (const float*)d_in[11];
    const float* bn_b    = (const float*)d_in[12];
    const float* bn_m    = (const float*)d_in[13];
    const float* bn_v    = (const float*)d_in[14];
    const float* dense_w = (const float*)d_in[15];
    const float* dense_b = (const float*)d_in[16];
    float* out = (float*)d_out;

    const int SMEM = 3 * 32768;
    cudaFuncSetAttribute(k_gemm<true>,  cudaFuncAttributeMaxDynamicSharedMemorySize, SMEM);
    cudaFuncSetAttribute(k_gemm<false>, cudaFuncAttributeMaxDynamicSharedMemorySize, SMEM);

    __nv_bfloat16 *p_A, *p_B, *p_Ax, *p_Bd;
    float *p_conv;
    cudaGetSymbolAddress((void**)&p_A, g_A);
    cudaGetSymbolAddress((void**)&p_B, g_B);
    cudaGetSymbolAddress((void**)&p_Ax, g_Ax);
    cudaGetSymbolAddress((void**)&p_Bd, g_Bd);
    cudaGetSymbolAddress((void**)&p_conv, g_conv);

    k_normalize<<<(NV * CIN + 255) / 256, 256>>>(signal, nmean, nvar);

    const float* Ws[3] = {w0, w1, w2};
    const float* bs[3] = {b0, b1, b2};
    const int    Cs[3] = {CIN, TT, TT};
    const int    KTs[3] = {KT_CONV1, KT_CONV23, KT_CONV23};

    int patchGrid = (NV * RA + 7) / 8;
    dim3 convGrid(7, 54);   // N=800 -> 7 tiles, M=6890 -> 54 tiles

    for (int blk = 0; blk < 3; blk++) {
        int C = Cs[blk];
        int K = RA * C;
        k_patch<<<patchGrid, 256>>>(bc_idx, bc_w, C, KTs[blk]);
        k_buildB<<<(K * NCOL + 255) / 256, 256>>>(Ws[blk], C, KTs[blk]);
        k_gemm<true><<<convGrid, 256, SMEM>>>(p_A, LDA, p_B, LDBC, bs[blk], TT,
                                              p_conv, NCOL, NV, NCOL, KTs[blk]);
        k_amp_bn<<<NV, 256>>>(bn_g, bn_b, bn_m, bn_v, blk);
    }

    // dense head
    k_buildDense<<<(TT * NV + 255) / 256, 256>>>(dense_w);
    dim3 denseGrid(54, 54);
    k_gemm<false><<<denseGrid, 256, SMEM>>>(p_Ax, LDAX, p_Bd, LDBD, dense_b, NV,
                                            out, NV, NV, NV, KT_DENSE);
}